// round 10
// baseline (speedup 1.0000x reference)
#include <cuda_runtime.h>
#include <stdint.h>

#define BB 16384
#define TT 128

// ---------------------------------------------------------------------------
// JAX threefry2x32 (exact integer reproduction, partitionable scheme)
// ---------------------------------------------------------------------------
__host__ __device__ __forceinline__ uint32_t rotl32(uint32_t x, int d) {
    return (x << d) | (x >> (32 - d));
}

__host__ __device__ __forceinline__ void threefry2x32(uint32_t k0, uint32_t k1,
                                                      uint32_t& x0, uint32_t& x1) {
    uint32_t k2 = k0 ^ k1 ^ 0x1BD11BDAu;
    x0 += k0; x1 += k1;
#define TF_R(r) { x0 += x1; x1 = rotl32(x1, (r)); x1 ^= x0; }
    TF_R(13) TF_R(15) TF_R(26) TF_R(6)
    x0 += k1; x1 += k2 + 1u;
    TF_R(17) TF_R(29) TF_R(16) TF_R(24)
    x0 += k2; x1 += k0 + 2u;
    TF_R(13) TF_R(15) TF_R(26) TF_R(6)
    x0 += k0; x1 += k1 + 3u;
    TF_R(17) TF_R(29) TF_R(16) TF_R(24)
    x0 += k1; x1 += k2 + 4u;
    TF_R(13) TF_R(15) TF_R(26) TF_R(6)
    x0 += k2; x1 += k0 + 5u;
#undef TF_R
}

// jax.random.uniform(key,(B,),f32)[b] under jax_threefry_partitionable=True
__device__ __forceinline__ float jax_uniform_at(uint32_t ka, uint32_t kb, int b) {
    uint32_t x0 = 0u, x1 = (uint32_t)b;
    threefry2x32(ka, kb, x0, x1);
    uint32_t bits = x0 ^ x1;
    uint32_t f = (bits >> 9) | 0x3F800000u;
    return __uint_as_float(f) - 1.0f;
}

// ---------------------------------------------------------------------------
// TWO rows per warp; lane handles 4 tokens of each row. Pos phase processes
// both rows (6 float4 loads in flight), then quat phase (8 float4 loads).
// Interleaved uses stop ptxas sinking row1 loads -> higher load duty cycle.
// Block = 128 threads = 4 warps = 8 rows; grid = BB/8.
// ---------------------------------------------------------------------------
__global__ __launch_bounds__(128) void rot_randomizer_kernel(
    const float* __restrict__ pos,   // [B,T,3]
    const float* __restrict__ quat,  // [B,T,4] xyzw
    float* __restrict__ pos_out,     // [B,T,3]
    float* __restrict__ quat_out,    // [B,T,4] xyzw
    float* __restrict__ R_out,       // [B,3,3]
    uint32_t k0a, uint32_t k0b, uint32_t k1a, uint32_t k1b,
    uint32_t k2a, uint32_t k2b, uint32_t k3a, uint32_t k3b)
{
    const int warp = threadIdx.x >> 5;
    const int lane = threadIdx.x & 31;
    const int b0 = (blockIdx.x * 4 + warp) * 2;
    const int b1 = b0 + 1;
    const unsigned FULL = 0xFFFFFFFFu;

    // ---------- RNG: 8 uniforms (4 per row) on lanes 0..7 ----------
    float u = 0.0f;
    if (lane < 8) {
        const int kidx = lane & 3;
        const int row  = (lane >= 4) ? b1 : b0;
        uint32_t ka = (kidx == 0) ? k0a : (kidx == 1) ? k1a : (kidx == 2) ? k2a : k3a;
        uint32_t kb = (kidx == 0) ? k0b : (kidx == 1) ? k1b : (kidx == 2) ? k2b : k3b;
        u = jax_uniform_at(ka, kb, row);
    }
    const float u0_0 = __shfl_sync(FULL, u, 0);
    const float u1_0 = __shfl_sync(FULL, u, 1);
    const float u2_0 = __shfl_sync(FULL, u, 2);
    const float u3_0 = __shfl_sync(FULL, u, 3);
    const float u0_1 = __shfl_sync(FULL, u, 4);
    const float u1_1 = __shfl_sync(FULL, u, 5);
    const float u2_1 = __shfl_sync(FULL, u, 6);
    const float u3_1 = __shfl_sync(FULL, u, 7);

    const float PI_F = 3.14159265358979323846f;
    const bool mask0 = u3_0 < 0.015625f;
    const bool mask1 = u3_1 < 0.015625f;
    const float ax0 = mask0 ? 0.0f : ((u0_0 * 2.0f) * PI_F - PI_F);
    const float ay0 = mask0 ? 0.0f : ((u1_0 * 2.0f) * PI_F - PI_F);
    const float az0 = mask0 ? 0.0f : ((u2_0 * 2.0f) * PI_F - PI_F);
    const float ax1 = mask1 ? 0.0f : ((u0_1 * 2.0f) * PI_F - PI_F);
    const float ay1 = mask1 ? 0.0f : ((u1_1 * 2.0f) * PI_F - PI_F);
    const float az1 = mask1 ? 0.0f : ((u2_1 * 2.0f) * PI_F - PI_F);

    // ---------- 12 accurate sincos on lanes 0..11 ----------
    // lane 0..5: row0 {ax, ay, az, ax/2, ay/2, az/2}; lane 6..11: row1 same.
    float amine = 0.0f;
    {
        const bool r1 = lane >= 6;
        const int l6 = r1 ? lane - 6 : lane;
        const float AX = r1 ? ax1 : ax0;
        const float AY = r1 ? ay1 : ay0;
        const float AZ = r1 ? az1 : az0;
        if (lane < 12) {
            amine = (l6 == 0) ? AX : (l6 == 1) ? AY : (l6 == 2) ? AZ :
                    (l6 == 3) ? 0.5f * AX : (l6 == 4) ? 0.5f * AY : 0.5f * AZ;
        }
    }
    float s_, c_;
    sincosf(amine, &s_, &c_);  // fast __sincosf flips argmax signs -> fails
    const float sx_0  = __shfl_sync(FULL, s_, 0),  cx_0  = __shfl_sync(FULL, c_, 0);
    const float sy_0  = __shfl_sync(FULL, s_, 1),  cy_0  = __shfl_sync(FULL, c_, 1);
    const float sz_0  = __shfl_sync(FULL, s_, 2),  cz_0  = __shfl_sync(FULL, c_, 2);
    const float sx2_0 = __shfl_sync(FULL, s_, 3),  cx2_0 = __shfl_sync(FULL, c_, 3);
    const float sy2_0 = __shfl_sync(FULL, s_, 4),  cy2_0 = __shfl_sync(FULL, c_, 4);
    const float sz2_0 = __shfl_sync(FULL, s_, 5),  cz2_0 = __shfl_sync(FULL, c_, 5);
    const float sx_1  = __shfl_sync(FULL, s_, 6),  cx_1  = __shfl_sync(FULL, c_, 6);
    const float sy_1  = __shfl_sync(FULL, s_, 7),  cy_1  = __shfl_sync(FULL, c_, 7);
    const float sz_1  = __shfl_sync(FULL, s_, 8),  cz_1  = __shfl_sync(FULL, c_, 8);
    const float sx2_1 = __shfl_sync(FULL, s_, 9),  cx2_1 = __shfl_sync(FULL, c_, 9);
    const float sy2_1 = __shfl_sync(FULL, s_, 10), cy2_1 = __shfl_sync(FULL, c_, 10);
    const float sz2_1 = __shfl_sync(FULL, s_, 11), cz2_1 = __shfl_sync(FULL, c_, 11);

    // --- R matrices (same expressions as the passing kernels) ---
#define MAKE_R(sfx) \
    const float r00##sfx = cz##sfx * cy##sfx; \
    const float r01##sfx = (cz##sfx * sy##sfx) * sx##sfx - sz##sfx * cx##sfx; \
    const float r02##sfx = (cz##sfx * sy##sfx) * cx##sfx + sz##sfx * sx##sfx; \
    const float r10##sfx = sz##sfx * cy##sfx; \
    const float r11##sfx = (sz##sfx * sy##sfx) * sx##sfx + cz##sfx * cx##sfx; \
    const float r12##sfx = (sz##sfx * sy##sfx) * cx##sfx - cz##sfx * sx##sfx; \
    const float r20##sfx = -sy##sfx; \
    const float r21##sfx = cy##sfx * sx##sfx; \
    const float r22##sfx = cy##sfx * cx##sfx;
    MAKE_R(_0)
    MAKE_R(_1)
#undef MAKE_R

    if (lane == 0) {
        float* Ro = R_out + b0 * 9;
        Ro[0] = r00_0; Ro[1] = r01_0; Ro[2] = r02_0;
        Ro[3] = r10_0; Ro[4] = r11_0; Ro[5] = r12_0;
        Ro[6] = r20_0; Ro[7] = r21_0; Ro[8] = r22_0;
    } else if (lane == 1) {
        float* Ro = R_out + b1 * 9;
        Ro[0] = r00_1; Ro[1] = r01_1; Ro[2] = r02_1;
        Ro[3] = r10_1; Ro[4] = r11_1; Ro[5] = r12_1;
        Ro[6] = r20_1; Ro[7] = r21_1; Ro[8] = r22_1;
    }

    // --- r_q per row, wxyz ---
#define MAKE_RQ(sfx) \
    const float w1##sfx  = cy2##sfx * cx2##sfx; \
    const float x1q##sfx = cy2##sfx * sx2##sfx; \
    const float y1q##sfx = cx2##sfx * sy2##sfx; \
    const float z1q##sfx = -sy2##sfx * sx2##sfx; \
    const float rw##sfx = cz2##sfx * w1##sfx  - sz2##sfx * z1q##sfx; \
    const float rx##sfx = cz2##sfx * x1q##sfx - sz2##sfx * y1q##sfx; \
    const float ry##sfx = cz2##sfx * y1q##sfx + sz2##sfx * x1q##sfx; \
    const float rz##sfx = cz2##sfx * z1q##sfx + sz2##sfx * w1##sfx;
    MAKE_RQ(_0)
    MAKE_RQ(_1)
#undef MAKE_RQ

    // ================== POS PHASE: both rows (6 loads in flight) ==========
    const int off0 = b0 * (TT * 3) + lane * 12;
    const int off1 = b1 * (TT * 3) + lane * 12;
    {
        const float4 A0 = *reinterpret_cast<const float4*>(pos + off0);
        const float4 B0 = *reinterpret_cast<const float4*>(pos + off0 + 4);
        const float4 C0 = *reinterpret_cast<const float4*>(pos + off0 + 8);
        const float4 A1 = *reinterpret_cast<const float4*>(pos + off1);
        const float4 B1 = *reinterpret_cast<const float4*>(pos + off1 + 4);
        const float4 C1 = *reinterpret_cast<const float4*>(pos + off1 + 8);

#define POS_ROW(A, Bv, C, off, s) { \
        const float p0x = A.x,  p0y = A.y,  p0z = A.z; \
        const float p1x = A.w,  p1y = Bv.x, p1z = Bv.y; \
        const float p2x = Bv.z, p2y = Bv.w, p2z = C.x; \
        const float p3x = C.y,  p3y = C.z,  p3z = C.w; \
        float4 D, E, F; \
        D.x = r00##s * p0x + r01##s * p0y + r02##s * p0z; \
        D.y = r10##s * p0x + r11##s * p0y + r12##s * p0z; \
        D.z = r20##s * p0x + r21##s * p0y + r22##s * p0z; \
        D.w = r00##s * p1x + r01##s * p1y + r02##s * p1z; \
        E.x = r10##s * p1x + r11##s * p1y + r12##s * p1z; \
        E.y = r20##s * p1x + r21##s * p1y + r22##s * p1z; \
        E.z = r00##s * p2x + r01##s * p2y + r02##s * p2z; \
        E.w = r10##s * p2x + r11##s * p2y + r12##s * p2z; \
        F.x = r20##s * p2x + r21##s * p2y + r22##s * p2z; \
        F.y = r00##s * p3x + r01##s * p3y + r02##s * p3z; \
        F.z = r10##s * p3x + r11##s * p3y + r12##s * p3z; \
        F.w = r20##s * p3x + r21##s * p3y + r22##s * p3z; \
        *reinterpret_cast<float4*>(pos_out + off)     = D; \
        *reinterpret_cast<float4*>(pos_out + off + 4) = E; \
        *reinterpret_cast<float4*>(pos_out + off + 8) = F; }

        POS_ROW(A0, B0, C0, off0, _0)
        POS_ROW(A1, B1, C1, off1, _1)
#undef POS_ROW
    }

    // ================== QUAT PHASE: both rows (8 loads in flight) =========
    {
        const int qoff0 = b0 * (TT * 4) + lane * 16;
        const int qoff1 = b1 * (TT * 4) + lane * 16;
        const float4* qi0 = reinterpret_cast<const float4*>(quat + qoff0);
        const float4* qi1 = reinterpret_cast<const float4*>(quat + qoff1);
        float4* qo0 = reinterpret_cast<float4*>(quat_out + qoff0);
        float4* qo1 = reinterpret_cast<float4*>(quat_out + qoff1);

        float4 qa0 = qi0[0], qa1 = qi0[1], qa2 = qi0[2], qa3 = qi0[3];
        float4 qb0 = qi1[0], qb1 = qi1[1], qb2 = qi1[2], qb3 = qi1[3];

#define QUAT_ONE(q, dst, s) { \
        const float qx = q.x, qy = q.y, qz = q.z, qw = q.w; \
        const float pw = rw##s * qw - rx##s * qx - ry##s * qy - rz##s * qz; \
        const float px = rw##s * qx + rx##s * qw + ry##s * qz - rz##s * qy; \
        const float py = rw##s * qy - rx##s * qz + ry##s * qw + rz##s * qx; \
        const float pz = rw##s * qz + rx##s * qy - ry##s * qx + rz##s * qw; \
        const float aw = fabsf(pw), axv = fabsf(px), ayv = fabsf(py), azv = fabsf(pz); \
        float bv = aw, bs = pw; \
        if (axv > bv) { bv = axv; bs = px; } \
        if (ayv > bv) { bv = ayv; bs = py; } \
        if (azv > bv) { bv = azv; bs = pz; } \
        const float n2 = qx * qx + qy * qy + qz * qz + qw * qw; \
        float f = rsqrtf(n2); \
        f = (bs < 0.0f) ? -f : f; \
        float4 o; o.x = px * f; o.y = py * f; o.z = pz * f; o.w = pw * f; \
        dst = o; }

        QUAT_ONE(qa0, qo0[0], _0)
        QUAT_ONE(qa1, qo0[1], _0)
        QUAT_ONE(qa2, qo0[2], _0)
        QUAT_ONE(qa3, qo0[3], _0)
        QUAT_ONE(qb0, qo1[0], _1)
        QUAT_ONE(qb1, qo1[1], _1)
        QUAT_ONE(qb2, qo1[2], _1)
        QUAT_ONE(qb3, qo1[3], _1)
#undef QUAT_ONE
    }
}

// ---------------------------------------------------------------------------
// Host: derive the four _build_R keys from seed 42 (partitionable threefry)
// ---------------------------------------------------------------------------
static void host_threefry(uint32_t k0, uint32_t k1, uint32_t x0, uint32_t x1,
                          uint32_t* o0, uint32_t* o1) {
    threefry2x32(k0, k1, x0, x1);
    *o0 = x0; *o1 = x1;
}

extern "C" void kernel_launch(void* const* d_in, const int* in_sizes, int n_in,
                              void* d_out, int out_size) {
    const float* pos  = (const float*)d_in[0];
    const float* quat = (const float*)d_in[1];
    float* out = (float*)d_out;

    // key = jax.random.key(42) -> (0, 42); sub = split(key)[1]
    uint32_t sa, sb;
    host_threefry(0u, 42u, 0u, 1u, &sa, &sb);

    // k = split(sub, 4): k[j] = full output pair of threefry(sub; 0, j)
    uint32_t kj[4][2];
    for (uint32_t j = 0; j < 4; j++) {
        host_threefry(sa, sb, 0u, j, &kj[j][0], &kj[j][1]);
    }

    float* pos_out  = out;
    float* quat_out = out + (size_t)BB * TT * 3;
    float* R_out    = out + (size_t)BB * TT * 7;

    rot_randomizer_kernel<<<BB / 8, 128>>>(
        pos, quat, pos_out, quat_out, R_out,
        kj[0][0], kj[0][1],
        kj[1][0], kj[1][1],
        kj[2][0], kj[2][1],
        kj[3][0], kj[3][1]);
}